// round 8
// baseline (speedup 1.0000x reference)
#include <cuda_runtime.h>
#include <cuda_fp16.h>
#include <math.h>
#include <stdint.h>

#define NPTS   400000
#define K27    27
#define TM     128
#define NTILES 3125     // 400000 / 128 exact

// ---------------- global scratch (static; no allocation allowed) ----------------
// activations live in fragment-permuted layout: 32 uint32 per row (128 B),
// slot index = tg*8 + ch*2 + hi, holding halves (16ch+2tg, 16ch+2tg+1) [hi: +8]
__device__ uint32_t g_f16[(size_t)NPTS * 32];   // features, permuted fp16
__device__ uint32_t g_h  [(size_t)NPTS * 32];   // layer-1 activations, permuted fp16 (ch3 zero)
__device__ uint4    g_W1q[27 * 5 * 2 * 32];     // W1 fragments: [k][nb][chpair][lane]
__device__ uint4    g_W2q[27 * 5 * 2 * 32];     // W2 fragments (chpair1.zw = 0)

// ---------------- fused sparse-conv layer, warp-owned register accumulation ----
// KCH: k16 chunks (4 or 3)
template<int KCH, bool DO_GELU>
__global__ void __launch_bounds__(256, 3) conv_reg(
    const uint4* __restrict__ in, const int* __restrict__ nbr,
    const uint4* __restrict__ Wq, void* __restrict__ outp)
{
    __shared__ int sNbr[K27 * TM];

    const int tid  = threadIdx.x;
    const int lane = tid & 31;
    const int warp = tid >> 5;
    const int base = blockIdx.x * TM;

    #pragma unroll
    for (int e = tid; e < K27 * TM; e += 256)
        sNbr[e] = nbr[(size_t)(e >> 7) * NPTS + base + (e & 127)];
    __syncthreads();

    const int gid  = lane >> 2;      // fragment row group 0..7
    const int tg   = lane & 3;       // fragment col group 0..3
    const int row0 = warp * 16 + gid;
    const int row1 = row0 + 8;

    float D[5][4];
    #pragma unroll
    for (int nb = 0; nb < 5; nb++)
        #pragma unroll
        for (int j = 0; j < 4; j++) D[nb][j] = 0.0f;

    #pragma unroll 1
    for (int k = 0; k < K27; k++) {
        const int s0 = sNbr[k * TM + row0];
        const int s1 = sNbr[k * TM + row1];
        const bool v0 = (s0 != NPTS);
        const bool v1 = (s1 != NPTS);
        if (!__ballot_sync(0xFFFFFFFFu, v0 || v1)) continue;

        // A: 2 x LDG.128 per row (fragment-permuted layout, 8 uint4 per row)
        uint4 q0 = make_uint4(0,0,0,0), q1 = q0, p0 = q0, p1 = q0;
        if (v0) {
            const uint4* rp = in + (size_t)s0 * 8 + tg * 2;
            q0 = rp[0]; q1 = rp[1];
        }
        if (v1) {
            const uint4* rp = in + (size_t)s1 * 8 + tg * 2;
            p0 = rp[0]; p1 = rp[1];
        }

        const uint4* wp = Wq + (size_t)k * 5 * 2 * 32 + lane;
        #pragma unroll
        for (int nb = 0; nb < 5; nb++) {
            const uint4 w0 = wp[(nb * 2 + 0) * 32];
            const uint4 w1 = wp[(nb * 2 + 1) * 32];
            // ch0
            asm volatile(
                "mma.sync.aligned.m16n8k16.row.col.f32.f16.f16.f32 "
                "{%0,%1,%2,%3}, {%4,%5,%6,%7}, {%8,%9}, {%0,%1,%2,%3};"
                : "+f"(D[nb][0]), "+f"(D[nb][1]), "+f"(D[nb][2]), "+f"(D[nb][3])
                : "r"(q0.x), "r"(p0.x), "r"(q0.y), "r"(p0.y), "r"(w0.x), "r"(w0.y));
            // ch1
            asm volatile(
                "mma.sync.aligned.m16n8k16.row.col.f32.f16.f16.f32 "
                "{%0,%1,%2,%3}, {%4,%5,%6,%7}, {%8,%9}, {%0,%1,%2,%3};"
                : "+f"(D[nb][0]), "+f"(D[nb][1]), "+f"(D[nb][2]), "+f"(D[nb][3])
                : "r"(q0.z), "r"(p0.z), "r"(q0.w), "r"(p0.w), "r"(w0.z), "r"(w0.w));
            // ch2
            asm volatile(
                "mma.sync.aligned.m16n8k16.row.col.f32.f16.f16.f32 "
                "{%0,%1,%2,%3}, {%4,%5,%6,%7}, {%8,%9}, {%0,%1,%2,%3};"
                : "+f"(D[nb][0]), "+f"(D[nb][1]), "+f"(D[nb][2]), "+f"(D[nb][3])
                : "r"(q1.x), "r"(p1.x), "r"(q1.y), "r"(p1.y), "r"(w1.x), "r"(w1.y));
            if (KCH == 4) {
                asm volatile(
                    "mma.sync.aligned.m16n8k16.row.col.f32.f16.f16.f32 "
                    "{%0,%1,%2,%3}, {%4,%5,%6,%7}, {%8,%9}, {%0,%1,%2,%3};"
                    : "+f"(D[nb][0]), "+f"(D[nb][1]), "+f"(D[nb][2]), "+f"(D[nb][3])
                    : "r"(q1.z), "r"(p1.z), "r"(q1.w), "r"(p1.w), "r"(w1.z), "r"(w1.w));
            }
        }
    }

    // ---- epilogue ----
    const int r0 = base + row0;
    const int r1 = base + row1;
    if (DO_GELU) {
        // write next-layer A directly in fragment-permuted layout
        uint32_t* hp = (uint32_t*)outp;   // 32 uint32 per row
        #pragma unroll
        for (int nb = 0; nb < 5; nb++) {
            const int t   = nb * 4 + tg;          // pair index 0..19
            const int ch  = t >> 3;
            const int pt  = t & 7;
            const int tg2 = (pt < 4) ? pt : pt - 4;
            const int hi  = (pt < 4) ? 0 : 1;
            const int idx = tg2 * 8 + ch * 2 + hi;
            float x0 = D[nb][0]; x0 *= normcdff(x0);
            float x1 = D[nb][1]; x1 *= normcdff(x1);
            float x2 = D[nb][2]; x2 *= normcdff(x2);
            float x3 = D[nb][3]; x3 *= normcdff(x3);
            __half2 h01 = __floats2half2_rn(x0, x1);
            __half2 h23 = __floats2half2_rn(x2, x3);
            hp[(size_t)r0 * 32 + idx] = *(uint32_t*)&h01;
            hp[(size_t)r1 * 32 + idx] = *(uint32_t*)&h23;
        }
        // zero pad slots tg*8 + {5,6,7} (ch2-hi and ch3)
        #pragma unroll
        for (int z = 5; z < 8; z++) {
            hp[(size_t)r0 * 32 + tg * 8 + z] = 0u;
            hp[(size_t)r1 * 32 + tg * 8 + z] = 0u;
        }
    } else {
        float* op = (float*)outp;
        #pragma unroll
        for (int nb = 0; nb < 5; nb++) {
            const int col = nb * 8 + tg * 2;
            if (col < 38) {
                *(float2*)(op + (size_t)r0 * 38 + col) = make_float2(D[nb][0], D[nb][1]);
                *(float2*)(op + (size_t)r1 * 38 + col) = make_float2(D[nb][2], D[nb][3]);
            }
        }
    }
}

// ---------------- one-time conversions ----------------
// features -> permuted fp16: one thread per half2 pair
__global__ void cvt_feat(const float* __restrict__ f) {
    size_t i = (size_t)blockIdx.x * blockDim.x + threadIdx.x;
    const size_t npairs = (size_t)NPTS * 32;
    if (i < npairs) {
        const size_t r = i >> 5;
        const int t = (int)(i & 31);
        const float2 v = *(const float2*)(f + r * 64 + t * 2);
        const int ch  = t >> 3;
        const int pt  = t & 7;
        const int tg2 = (pt < 4) ? pt : pt - 4;
        const int hi  = (pt < 4) ? 0 : 1;
        __half2 h = __floats2half2_rn(v.x, v.y);
        g_f16[r * 32 + tg2 * 8 + ch * 2 + hi] = *(uint32_t*)&h;
    }
}

// W fragment packing into uint4 chunk-pairs
template<int KW>
__device__ __forceinline__ void pack_q(const float* W, uint4* Wq, int i) {
    const int lane = i & 31, pair = (i >> 5) & 1, nb = (i >> 6) % 5, k = i / (2 * 5 * 32);
    const int n = nb * 8 + (lane >> 2);
    const float* Wk = W + (size_t)k * KW * 38;
    auto val = [&](int kk) -> float {
        return (n < 38 && kk < KW) ? Wk[kk * 38 + n] : 0.0f;
    };
    uint32_t r[4];
    #pragma unroll
    for (int c = 0; c < 2; c++) {
        const int kk0 = (pair * 2 + c) * 16 + (lane & 3) * 2;
        __half2 lo = __floats2half2_rn(val(kk0),     val(kk0 + 1));
        __half2 hi = __floats2half2_rn(val(kk0 + 8), val(kk0 + 9));
        r[c * 2 + 0] = *(uint32_t*)&lo;
        r[c * 2 + 1] = *(uint32_t*)&hi;
    }
    Wq[i] = make_uint4(r[0], r[1], r[2], r[3]);
}
__global__ void cvt_w(const float* __restrict__ W1, const float* __restrict__ W2) {
    int i = blockIdx.x * blockDim.x + threadIdx.x;
    if (i < 27 * 5 * 2 * 32) {
        pack_q<64>(W1, g_W1q, i);
        pack_q<38>(W2, g_W2q, i);
    }
}

extern "C" void kernel_launch(void* const* d_in, const int* in_sizes, int n_in,
                              void* d_out, int out_size)
{
    const float* feat = nullptr;
    const int*   nbr  = nullptr;
    const float* W1   = nullptr;
    const float* W2   = nullptr;
    for (int i = 0; i < n_in; i++) {
        long s = in_sizes[i];
        if      (s == (long)NPTS * 64)      feat = (const float*)d_in[i];
        else if (s == (long)K27 * NPTS)     nbr  = (const int*)d_in[i];
        else if (s == (long)27 * 64 * 38)   W1   = (const float*)d_in[i];
        else if (s == (long)27 * 38 * 38)   W2   = (const float*)d_in[i];
    }
    float* out = (float*)d_out;
    uint32_t *f16p, *hp;
    uint4 *w1p, *w2p;
    cudaGetSymbolAddress((void**)&f16p, g_f16);
    cudaGetSymbolAddress((void**)&hp,   g_h);
    cudaGetSymbolAddress((void**)&w1p,  g_W1q);
    cudaGetSymbolAddress((void**)&w2p,  g_W2q);

    cvt_feat<<<(int)(((size_t)NPTS * 32 + 255) / 256), 256>>>(feat);
    cvt_w<<<(27 * 5 * 2 * 32 + 255) / 256, 256>>>(W1, W2);
    conv_reg<4, true ><<<NTILES, 256>>>((const uint4*)f16p, nbr, w1p, hp);
    conv_reg<3, false><<<NTILES, 256>>>((const uint4*)hp,   nbr, w2p, out);
}

// round 13
// speedup vs baseline: 1.0433x; 1.0433x over previous
#include <cuda_runtime.h>
#include <cuda_fp16.h>
#include <math.h>
#include <stdint.h>

#define NPTS   400000
#define K27    27
#define TM     256
#define NT     1563      // ceil(400000/256)

// ---------------- global scratch (static; no allocation allowed) ----------------
__device__ __half g_f16[(size_t)NPTS * 64];     // features fp16 (natural layout)
__device__ __half g_h  [(size_t)NPTS * 48];     // layer-1 activations fp16, padded to 48
__device__ uint2  g_W1f[27 * 5 * 4 * 32];       // fragment-packed W1: [k][nb][ch][lane]
__device__ uint2  g_W2f[27 * 5 * 3 * 32];       // fragment-packed W2

// ---------------- fused sparse-conv layer, 32 rows/warp, register accumulation --
// CIN: fp16 row width (64 or 48), KCH: k16 chunks (4 or 3)
template<int CIN, int KCH, bool DO_GELU>
__global__ void __launch_bounds__(256, 2) conv_reg(
    const __half* __restrict__ in, const int* __restrict__ nbr,
    const uint2* __restrict__ Wf, void* __restrict__ outp)
{
    __shared__ int sNbr[K27 * TM];

    const int tid  = threadIdx.x;
    const int lane = tid & 31;
    const int warp = tid >> 5;
    const int base = blockIdx.x * TM;

    #pragma unroll
    for (int e = tid; e < K27 * TM; e += 256) {
        const int r = base + (e & (TM - 1));
        sNbr[e] = (r < NPTS) ? nbr[(size_t)(e >> 8) * NPTS + r] : NPTS;
    }
    __syncthreads();

    const int gid  = lane >> 2;      // fragment row group 0..7
    const int tg   = lane & 3;       // fragment col group 0..3
    const int row0 = warp * 32 + gid;

    float D0[5][4], D1[5][4];
    #pragma unroll
    for (int nb = 0; nb < 5; nb++)
        #pragma unroll
        for (int j = 0; j < 4; j++) { D0[nb][j] = 0.0f; D1[nb][j] = 0.0f; }

    #pragma unroll 1
    for (int k = 0; k < K27; k++) {
        const int s0 = sNbr[k * TM + row0];
        const int s1 = sNbr[k * TM + row0 + 8];
        const int s2 = sNbr[k * TM + row0 + 16];
        const int s3 = sNbr[k * TM + row0 + 24];
        const bool v0 = (s0 != NPTS), v1 = (s1 != NPTS);
        const bool v2 = (s2 != NPTS), v3 = (s3 != NPTS);
        if (!__ballot_sync(0xFFFFFFFFu, v0 || v1 || v2 || v3)) continue;

        const __half* p0 = in + (size_t)s0 * CIN + tg * 2;
        const __half* p1 = in + (size_t)s1 * CIN + tg * 2;
        const __half* p2 = in + (size_t)s2 * CIN + tg * 2;
        const __half* p3 = in + (size_t)s3 * CIN + tg * 2;
        const uint2* wp = Wf + (size_t)k * 5 * KCH * 32 + lane;

        #pragma unroll
        for (int ch = 0; ch < KCH; ch++) {
            const int off = ch * 16;
            // A fragments for both 16-row blocks of this chunk
            const uint32_t a0 = v0 ? *(const uint32_t*)(p0 + off)     : 0u;
            const uint32_t a1 = v1 ? *(const uint32_t*)(p1 + off)     : 0u;
            const uint32_t a2 = v0 ? *(const uint32_t*)(p0 + off + 8) : 0u;
            const uint32_t a3 = v1 ? *(const uint32_t*)(p1 + off + 8) : 0u;
            const uint32_t b0 = v2 ? *(const uint32_t*)(p2 + off)     : 0u;
            const uint32_t b1 = v3 ? *(const uint32_t*)(p3 + off)     : 0u;
            const uint32_t b2 = v2 ? *(const uint32_t*)(p2 + off + 8) : 0u;
            const uint32_t b3 = v3 ? *(const uint32_t*)(p3 + off + 8) : 0u;

            #pragma unroll
            for (int nb = 0; nb < 5; nb++) {
                const uint2 w = wp[(nb * KCH + ch) * 32];   // loaded once, used twice
                asm volatile(
                    "mma.sync.aligned.m16n8k16.row.col.f32.f16.f16.f32 "
                    "{%0,%1,%2,%3}, {%4,%5,%6,%7}, {%8,%9}, {%0,%1,%2,%3};"
                    : "+f"(D0[nb][0]), "+f"(D0[nb][1]), "+f"(D0[nb][2]), "+f"(D0[nb][3])
                    : "r"(a0), "r"(a1), "r"(a2), "r"(a3), "r"(w.x), "r"(w.y));
                asm volatile(
                    "mma.sync.aligned.m16n8k16.row.col.f32.f16.f16.f32 "
                    "{%0,%1,%2,%3}, {%4,%5,%6,%7}, {%8,%9}, {%0,%1,%2,%3};"
                    : "+f"(D1[nb][0]), "+f"(D1[nb][1]), "+f"(D1[nb][2]), "+f"(D1[nb][3])
                    : "r"(b0), "r"(b1), "r"(b2), "r"(b3), "r"(w.x), "r"(w.y));
            }
        }
    }

    // ---- epilogue ----
    const int r0 = base + row0;          // D0 rows: r0, r0+8 ; D1 rows: r0+16, r0+24
    if (DO_GELU) {
        uint32_t* hp = (uint32_t*)g_h;   // row stride 24 uint32 (48 halves)
        #pragma unroll
        for (int blk = 0; blk < 2; blk++) {
            float (*D)[4] = blk ? D1 : D0;
            const int ra = r0 + blk * 16, rb = ra + 8;
            #pragma unroll
            for (int nb = 0; nb < 5; nb++) {
                const int cw = (nb * 8 + tg * 2) >> 1;
                float x0 = D[nb][0]; x0 *= normcdff(x0);
                float x1 = D[nb][1]; x1 *= normcdff(x1);
                float x2 = D[nb][2]; x2 *= normcdff(x2);
                float x3 = D[nb][3]; x3 *= normcdff(x3);
                __half2 hA = __floats2half2_rn(x0, x1);
                __half2 hB = __floats2half2_rn(x2, x3);
                if (ra < NPTS) hp[(size_t)ra * 24 + cw] = *(uint32_t*)&hA;
                if (rb < NPTS) hp[(size_t)rb * 24 + cw] = *(uint32_t*)&hB;
            }
            if (ra < NPTS) hp[(size_t)ra * 24 + 20 + tg] = 0u;   // pad cols 40..47
            if (rb < NPTS) hp[(size_t)rb * 24 + 20 + tg] = 0u;
        }
    } else {
        float* op = (float*)outp;
        #pragma unroll
        for (int blk = 0; blk < 2; blk++) {
            float (*D)[4] = blk ? D1 : D0;
            const int ra = r0 + blk * 16, rb = ra + 8;
            #pragma unroll
            for (int nb = 0; nb < 5; nb++) {
                const int col = nb * 8 + tg * 2;
                if (col < 38) {
                    if (ra < NPTS)
                        *(float2*)(op + (size_t)ra * 38 + col) = make_float2(D[nb][0], D[nb][1]);
                    if (rb < NPTS)
                        *(float2*)(op + (size_t)rb * 38 + col) = make_float2(D[nb][2], D[nb][3]);
                }
            }
        }
    }
}

// ---------------- one-time conversions ----------------
__global__ void cvt_feat(const float* __restrict__ f) {
    size_t i = (size_t)blockIdx.x * blockDim.x + threadIdx.x;
    const size_t n4 = (size_t)NPTS * 64 / 4;
    if (i < n4) {
        float4 v = ((const float4*)f)[i];
        __half2* o = (__half2*)g_f16;
        o[i * 2 + 0] = __floats2half2_rn(v.x, v.y);
        o[i * 2 + 1] = __floats2half2_rn(v.z, v.w);
    }
}

// fragment packing: per (k, nb, ch, lane): n = nb*8 + lane/4, kk0 = ch*16 + (lane%4)*2
// b0 = (W[kk0][n], W[kk0+1][n]); b1 = (W[kk0+8][n], W[kk0+9][n])
template<int KW, int KCH>
__device__ __forceinline__ void pack_one(const float* W, uint2* Wf, int i) {
    int lane = i & 31, ch = (i >> 5) % KCH, nb = (i / (32 * KCH)) % 5, k = i / (32 * KCH * 5);
    int n = nb * 8 + (lane >> 2);
    int kk0 = ch * 16 + (lane & 3) * 2;
    const float* Wk = W + (size_t)k * KW * 38;
    auto val = [&](int kk) -> float {
        return (n < 38 && kk < KW) ? Wk[kk * 38 + n] : 0.0f;
    };
    __half2 b0 = __floats2half2_rn(val(kk0),     val(kk0 + 1));
    __half2 b1 = __floats2half2_rn(val(kk0 + 8), val(kk0 + 9));
    Wf[i] = make_uint2(*(uint32_t*)&b0, *(uint32_t*)&b1);
}
__global__ void cvt_w(const float* __restrict__ W1, const float* __restrict__ W2) {
    int i = blockIdx.x * blockDim.x + threadIdx.x;
    if (i < 27 * 5 * 4 * 32) pack_one<64, 4>(W1, g_W1f, i);
    if (i < 27 * 5 * 3 * 32) pack_one<38, 3>(W2, g_W2f, i);
}

extern "C" void kernel_launch(void* const* d_in, const int* in_sizes, int n_in,
                              void* d_out, int out_size)
{
    const float* feat = nullptr;
    const int*   nbr  = nullptr;
    const float* W1   = nullptr;
    const float* W2   = nullptr;
    for (int i = 0; i < n_in; i++) {
        long s = in_sizes[i];
        if      (s == (long)NPTS * 64)      feat = (const float*)d_in[i];
        else if (s == (long)K27 * NPTS)     nbr  = (const int*)d_in[i];
        else if (s == (long)27 * 64 * 38)   W1   = (const float*)d_in[i];
        else if (s == (long)27 * 38 * 38)   W2   = (const float*)d_in[i];
    }
    float* out = (float*)d_out;
    __half *f16p, *hp;
    uint2 *w1p, *w2p;
    cudaGetSymbolAddress((void**)&f16p, g_f16);
    cudaGetSymbolAddress((void**)&hp,   g_h);
    cudaGetSymbolAddress((void**)&w1p,  g_W1f);
    cudaGetSymbolAddress((void**)&w2p,  g_W2f);

    cvt_feat<<<(NPTS * 64 / 4 + 255) / 256, 256>>>(feat);
    cvt_w<<<(27 * 5 * 4 * 32 + 255) / 256, 256>>>(W1, W2);
    conv_reg<64, 4, true ><<<NT, 256>>>(f16p, nbr, w1p, hp);
    conv_reg<48, 3, false><<<NT, 256>>>(hp,   nbr, w2p, out);
}